// round 3
// baseline (speedup 1.0000x reference)
#include <cuda_runtime.h>
#include <cooperative_groups.h>

#define BB 8
#define HH 256
#define WW 256
#define NPIX (BB*HH*WW)
#define N_ITERS 200
#define TILE_W 64
#define TILE_H 32
#define VPT 8              // rows per thread
#define NCTAS 256          // 8 images * (4 x 8) tiles
#define NTHREADS 256       // 64 x 4 threads per tile

// Double-buffered ubar halo exchange buffer (alloc-free scratch)
__device__ float g_halo[2][NPIX];
// Per-tile progress flags, one per 128B line
__device__ int   g_flags[NCTAS * 32];

__device__ __forceinline__ int ld_acquire_gpu(const int* p) {
    int v;
    asm volatile("ld.acquire.gpu.global.s32 %0, [%1];" : "=r"(v) : "l"(p) : "memory");
    return v;
}
__device__ __forceinline__ void st_release_gpu(int* p, int v) {
    asm volatile("st.release.gpu.global.s32 [%0], %1;" :: "l"(p), "r"(v) : "memory");
}
__device__ __forceinline__ float ldcg(const float* p) {
    float v;
    asm volatile("ld.global.cg.f32 %0, [%1];" : "=f"(v) : "l"(p) : "memory");
    return v;
}
__device__ __forceinline__ void wait_flag(int* p, int target) {
    while (ld_acquire_gpu(p) - target < 0) { }
}
__device__ __forceinline__ float clipf(float v, float b) {
    return fminf(fmaxf(v, -b), b);
}

__global__ __launch_bounds__(NTHREADS, 2)
void tv_persist(const float* __restrict__ f,
                const float* __restrict__ lam,
                float* __restrict__ out)
{
    const float SIG  = 0.35355339f;
    const float TAUc = 0.35355339f;
    const float INV  = 1.0f / (1.0f + TAUc);

    __shared__ float ubs[TILE_H][TILE_W + 1];   // interior ubar tile

    const int c  = blockIdx.x;
    const int b  = c >> 5;           // image
    const int t  = c & 31;           // tile within image
    const int j0 = (t & 3) * TILE_W;
    const int i0 = (t >> 2) * TILE_H;
    const int tx = threadIdx.x & 63;
    const int ty = threadIdx.x >> 6; // 0..3
    const int j    = j0 + tx;
    const int itop = i0 + ty * VPT;

    const int base = (b * HH + itop) * WW + j;   // pixel k at base + k*WW
    const int r0   = ty * VPT;                    // smem row of my first pixel

    const bool has_up = (i0 > 0);
    const bool has_dn = (i0 + TILE_H < HH);
    const bool has_lf = (j0 > 0);
    const bool has_rt = (j0 + TILE_W < WW);

    int* myflag = &g_flags[c * 32];
    int* upflag = &g_flags[(c - 4) * 32];
    int* dnflag = &g_flags[(c + 4) * 32];
    int* lfflag = &g_flags[(c - 1) * 32];
    int* rtflag = &g_flags[(c + 1) * 32];

    // Epoch: flags are monotone across graph replays; all tiles ended the
    // previous run at the same value.
    const int epoch = *(volatile int*)myflag;

    // ---- Load all state into registers ----
    float u[VPT], ub[VPT], pc[VPT], qc[VPT], ql[VPT];
    float fv[VPT], lamx[VPT], lamy[VPT], lams[VPT];
#pragma unroll
    for (int k = 0; k < VPT; k++) {
        const int i   = itop + k;
        const int idx = base + k * WW;
        float fk = f[idx];
        u[k] = ub[k] = fv[k] = fk;
        pc[k] = qc[k] = ql[k] = 0.f;
        lamx[k] = (i < HH - 1) ? lam[idx + WW] : 0.f;   // bound for p(i,j)
        lamy[k] = (j < WW - 1) ? lam[idx + 1]  : 0.f;   // bound for q(i,j)
        lams[k] = (j > 0)      ? lam[idx]      : 0.f;   // bound for q(i,j-1)
    }
    float pu_top = 0.f;                                  // p(itop-1, j)
    const float pu_lam = (itop > 0) ? lam[base] : 0.f;

    for (int it = 0; it < N_ITERS; it++) {
        float* H = g_halo[it & 1];

        // ---- stage interior ubar into SMEM ----
#pragma unroll
        for (int k = 0; k < VPT; k++) ubs[r0 + k][tx] = ub[k];

        // ---- publish tile-boundary ubar to global halo (parity buffer) ----
        bool pub = false;
        if (ty == 0) { H[base] = ub[0]; pub = true; }
        if (ty == 3) { H[base + (VPT - 1) * WW] = ub[VPT - 1]; pub = true; }
        if (tx == 0 || tx == 63) {
#pragma unroll
            for (int k = 0; k < VPT; k++) H[base + k * WW] = ub[k];
            pub = true;
        }
        if (pub) __threadfence();

        __syncthreads();   // publishes + smem staging complete

        const int target = epoch + it + 1;
        if (threadIdx.x == 0) st_release_gpu(myflag, target);

        // Only the threads that read a given halo wait for it.
        if (ty == 0  && has_up) wait_flag(upflag, target);
        if (ty == 3  && has_dn) wait_flag(dnflag, target);
        if (tx == 0  && has_lf) wait_flag(lfflag, target);
        if (tx == 63 && has_rt) wait_flag(rtflag, target);

        const float* Hc = g_halo[it & 1];

        // ---- gather cross-thread / cross-tile neighbor values ----
        float ub_above = (ty > 0) ? ubs[r0 - 1][tx]
                        : (has_up ? ldcg(&Hc[base - WW]) : 0.f);
        float ub_below = (ty < 3) ? ubs[r0 + VPT][tx]
                        : (has_dn ? ldcg(&Hc[base + VPT * WW]) : 0.f);

        // ---- one Chambolle-Pock iteration in registers ----
        pu_top = clipf(pu_top + SIG * (ub[0] - ub_above), pu_lam);
        float pu = pu_top;
#pragma unroll
        for (int k = 0; k < VPT; k++) {
            float ub_b = (k < VPT - 1) ? ub[k + 1] : ub_below;
            float ub_l = (tx > 0)  ? ubs[r0 + k][tx - 1]
                       : (has_lf ? ldcg(&Hc[base + k * WW - 1]) : 0.f);
            float ub_r = (tx < 63) ? ubs[r0 + k][tx + 1]
                       : (has_rt ? ldcg(&Hc[base + k * WW + 1]) : 0.f);

            pc[k] = clipf(pc[k] + SIG * (ub_b - ub[k]), lamx[k]);
            qc[k] = clipf(qc[k] + SIG * (ub_r - ub[k]), lamy[k]);
            ql[k] = clipf(ql[k] + SIG * (ub[k] - ub_l), lams[k]);

            float div = (pu - pc[k]) + (ql[k] - qc[k]);
            float un  = (u[k] + TAUc * (fv[k] - div)) * INV;
            ub[k] = 2.f * un - u[k];
            u[k]  = un;
            pu    = pc[k];
        }
        __syncthreads();   // SMEM WAR before next iteration's staging
    }

#pragma unroll
    for (int k = 0; k < VPT; k++) out[base + k * WW] = u[k];
}

extern "C" void kernel_launch(void* const* d_in, const int* in_sizes, int n_in,
                              void* d_out, int out_size) {
    const float* f   = (const float*)d_in[0];
    const float* lam = (const float*)d_in[1];
    float* out = (float*)d_out;

    // Cooperative launch used only to guarantee全-grid co-residency
    // (required for the point-to-point flag protocol); grid.sync is not used.
    void* args[] = { (void*)&f, (void*)&lam, (void*)&out };
    cudaLaunchCooperativeKernel((void*)tv_persist,
                                dim3(NCTAS), dim3(NTHREADS),
                                args, 0, 0);
}

// round 4
// speedup vs baseline: 1.9038x; 1.9038x over previous
#include <cuda_runtime.h>
#include <cooperative_groups.h>
#include <cstdint>
namespace cg = cooperative_groups;

#define BB 8
#define HH 256
#define WW 256
#define NPIX (BB*HH*WW)
#define N_ITERS 200

__device__ __forceinline__ float clipf(float v, float b) {
    return fminf(fmaxf(v, -b), b);
}

// ===================== FAST PATH: 16-CTA cluster per image =====================
// 8 clusters (one per image), 16 CTAs each = 128 CTAs, 512 threads, 8 px/thread.
// Halo exchange via DSMEM into neighbor's SMEM ring; one cluster.sync per iter.

#define C_THREADS 512
#define C_CTAS    (BB * 16)

__device__ __forceinline__ uint32_t smem_u32(const void* p) {
    return (uint32_t)__cvta_generic_to_shared(p);
}
__device__ __forceinline__ void dsmem_store(uint32_t laddr, uint32_t rank, float v) {
    uint32_t rem;
    asm volatile("mapa.shared::cluster.u32 %0, %1, %2;" : "=r"(rem) : "r"(laddr), "r"(rank));
    asm volatile("st.shared::cluster.f32 [%0], %1;" :: "r"(rem), "f"(v) : "memory");
}
__device__ __forceinline__ void cluster_sync_() {
    asm volatile("barrier.cluster.arrive.aligned;" ::: "memory");
    asm volatile("barrier.cluster.wait.aligned;"   ::: "memory");
}

__global__ __launch_bounds__(C_THREADS, 1)
void tv_cluster(const float* __restrict__ f,
                const float* __restrict__ lam,
                float* __restrict__ out)
{
    const float SIG  = 0.35355339f;
    const float TAUc = 0.35355339f;
    const float INV  = 1.0f / (1.0f + TAUc);

    // Double-buffered ubar tile with 1-wide halo ring:
    // rows 1..64 / cols 1..64 interior, row 0/65 + col 0/65 = ring.
    __shared__ float ubs[2][66][67];

    const int bid = blockIdx.x;
    const int img = bid >> 4;
    const int r   = bid & 15;        // rank within cluster
    const int tc  = r & 3;           // tile col (0..3)
    const int tr  = r >> 2;          // tile row (0..3)
    const int j0  = tc * 64;
    const int i0  = tr * 64;
    const int tid = threadIdx.x;
    const int tx  = tid & 63;
    const int ty  = tid >> 6;        // 0..7
    const int j    = j0 + tx;
    const int itop = i0 + ty * 8;
    const int base = (img * HH + itop) * WW + j;
    const int srow = 1 + ty * 8;

    // Zero both SMEM buffers (ring cells on image boundary stay 0 forever).
    for (int x = tid; x < 2 * 66 * 67; x += C_THREADS)
        ((float*)ubs)[x] = 0.f;

    // ---- Load all state into registers ----
    float u[8], ub[8], pc[8], qc[8], ql[8];
    float fv[8], lamx[8], lamy[8], lams[8];
#pragma unroll
    for (int k = 0; k < 8; k++) {
        const int i   = itop + k;
        const int idx = base + k * WW;
        float fk = f[idx];
        u[k] = ub[k] = fv[k] = fk;
        pc[k] = qc[k] = ql[k] = 0.f;
        lamx[k] = (i < HH - 1) ? lam[idx + WW] : 0.f;   // bound for p(i,j)
        lamy[k] = (j < WW - 1) ? lam[idx + 1]  : 0.f;   // bound for q(i,j)
        lams[k] = (j > 0)      ? lam[idx]      : 0.f;   // bound for q(i,j-1)
    }
    float pu_top = 0.f;
    const float pu_lam = (itop > 0) ? lam[base] : 0.f;

    const bool up = (tr > 0), dn = (tr < 3), lf = (tc > 0), rt = (tc < 3);

    // Ring zeros must be visible cluster-wide before any DSMEM store lands.
    cluster_sync_();

    for (int it = 0; it < N_ITERS; it++) {
        const int s = it & 1;

        // ---- stage interior ubar ----
#pragma unroll
        for (int k = 0; k < 8; k++) ubs[s][srow + k][1 + tx] = ub[k];

        // ---- export boundary ubar into neighbors' rings (DSMEM) ----
        if (ty == 0 && up) dsmem_store(smem_u32(&ubs[s][65][1 + tx]), r - 4, ub[0]);
        if (ty == 7 && dn) dsmem_store(smem_u32(&ubs[s][0][1 + tx]),  r + 4, ub[7]);
        if (tx == 0 && lf) {
#pragma unroll
            for (int k = 0; k < 8; k++)
                dsmem_store(smem_u32(&ubs[s][srow + k][65]), r - 1, ub[k]);
        }
        if (tx == 63 && rt) {
#pragma unroll
            for (int k = 0; k < 8; k++)
                dsmem_store(smem_u32(&ubs[s][srow + k][0]),  r + 1, ub[k]);
        }

        cluster_sync_();   // all stores (local + DSMEM) visible; doubles as CTA barrier

        // ---- one Chambolle-Pock iteration in registers ----
        float ub_above = ubs[s][srow - 1][1 + tx];
        pu_top = clipf(pu_top + SIG * (ub[0] - ub_above), pu_lam);
        float pu = pu_top;
#pragma unroll
        for (int k = 0; k < 8; k++) {
            float ub_b = (k < 7) ? ub[k + 1] : ubs[s][srow + 8][1 + tx];
            float ub_l = ubs[s][srow + k][tx];
            float ub_r = ubs[s][srow + k][tx + 2];

            pc[k] = clipf(pc[k] + SIG * (ub_b - ub[k]), lamx[k]);
            qc[k] = clipf(qc[k] + SIG * (ub_r - ub[k]), lamy[k]);
            ql[k] = clipf(ql[k] + SIG * (ub[k] - ub_l), lams[k]);

            float div = (pu - pc[k]) + (ql[k] - qc[k]);
            float un  = (u[k] + TAUc * (fv[k] - div)) * INV;
            ub[k] = 2.f * un - u[k];
            u[k]  = un;
            pu    = pc[k];
        }
        // No __syncthreads needed: double buffer + next iter's cluster.sync
        // separates this iter's reads from the t+2 overwrite of buffer s.
    }

#pragma unroll
    for (int k = 0; k < 8; k++) out[base + k * WW] = u[k];
}

// ===================== FALLBACK: R2 cooperative grid.sync kernel =====================

#define TILE_W 64
#define TILE_H 32
#define VPT 8
#define NCTAS 256
#define NTHREADS 256

__device__ float g_halo[2][NPIX];

__global__ __launch_bounds__(NTHREADS, 2)
void tv_persist(const float* __restrict__ f,
                const float* __restrict__ lam,
                float* __restrict__ out)
{
    cg::grid_group grid = cg::this_grid();

    const float SIG  = 0.35355339f;
    const float TAUc = 0.35355339f;
    const float INV  = 1.0f / (1.0f + TAUc);

    __shared__ float ubs[TILE_H + 2][TILE_W + 2];

    const int c  = blockIdx.x;
    const int b  = c >> 5;
    const int t  = c & 31;
    const int j0 = (t & 3) * TILE_W;
    const int i0 = (t >> 2) * TILE_H;
    const int tx = threadIdx.x & 63;
    const int ty = threadIdx.x >> 6;
    const int j    = j0 + tx;
    const int itop = i0 + ty * VPT;

    const int base = (b * HH + itop) * WW + j;
    const int srow = 1 + ty * VPT;

    float u[VPT], ub[VPT], pc[VPT], qc[VPT], ql[VPT];
    float fv[VPT], lamx[VPT], lamy[VPT], lams[VPT];
#pragma unroll
    for (int k = 0; k < VPT; k++) {
        const int i   = itop + k;
        const int idx = base + k * WW;
        float fk = f[idx];
        u[k] = ub[k] = fv[k] = fk;
        pc[k] = qc[k] = ql[k] = 0.f;
        lamx[k] = (i < HH - 1) ? lam[idx + WW] : 0.f;
        lamy[k] = (j < WW - 1) ? lam[idx + 1]  : 0.f;
        lams[k] = (j > 0)      ? lam[idx]      : 0.f;
    }
    float pu_top = 0.f;
    const float pu_lam = (itop > 0) ? lam[base] : 0.f;

    for (int it = 0; it < N_ITERS; it++) {
        float* H = g_halo[it & 1];
#pragma unroll
        for (int k = 0; k < VPT; k++) ubs[srow + k][1 + tx] = ub[k];

        if (ty == 0) H[base] = ub[0];
        if (ty == 3) H[base + (VPT - 1) * WW] = ub[VPT - 1];
        if (tx == 0 || tx == 63) {
#pragma unroll
            for (int k = 0; k < VPT; k++) H[base + k * WW] = ub[k];
        }

        grid.sync();

        const float* Hc = g_halo[it & 1];
        if (ty == 0)
            ubs[0][1 + tx]          = (i0 > 0)             ? Hc[base - WW]       : 0.f;
        if (ty == 3)
            ubs[TILE_H + 1][1 + tx] = (i0 + TILE_H < HH)   ? Hc[base + VPT * WW] : 0.f;
        if (tx == 0) {
#pragma unroll
            for (int k = 0; k < VPT; k++)
                ubs[srow + k][0]          = (j0 > 0)           ? Hc[base + k * WW - 1] : 0.f;
        }
        if (tx == 63) {
#pragma unroll
            for (int k = 0; k < VPT; k++)
                ubs[srow + k][TILE_W + 1] = (j0 + TILE_W < WW) ? Hc[base + k * WW + 1] : 0.f;
        }
        __syncthreads();

        float ub_above = ubs[srow - 1][1 + tx];
        pu_top = clipf(pu_top + SIG * (ub[0] - ub_above), pu_lam);
        float pu = pu_top;
#pragma unroll
        for (int k = 0; k < VPT; k++) {
            float ub_b = (k < VPT - 1) ? ub[k + 1] : ubs[srow + VPT][1 + tx];
            float ub_l = ubs[srow + k][tx];
            float ub_r = ubs[srow + k][2 + tx];

            pc[k] = clipf(pc[k] + SIG * (ub_b - ub[k]), lamx[k]);
            qc[k] = clipf(qc[k] + SIG * (ub_r - ub[k]), lamy[k]);
            ql[k] = clipf(ql[k] + SIG * (ub[k] - ub_l), lams[k]);

            float div = (pu - pc[k]) + (ql[k] - qc[k]);
            float un  = (u[k] + TAUc * (fv[k] - div)) * INV;
            ub[k] = 2.f * un - u[k];
            u[k]  = un;
            pu    = pc[k];
        }
        __syncthreads();
    }

#pragma unroll
    for (int k = 0; k < VPT; k++) out[base + k * WW] = u[k];
}

// ===================== host =====================

extern "C" void kernel_launch(void* const* d_in, const int* in_sizes, int n_in,
                              void* d_out, int out_size) {
    const float* f   = (const float*)d_in[0];
    const float* lam = (const float*)d_in[1];
    float* out = (float*)d_out;

    // Try the 16-CTA-cluster fast path; deterministic capability query.
    cudaFuncSetAttribute(tv_cluster, cudaFuncAttributeNonPortableClusterSizeAllowed, 1);

    cudaLaunchConfig_t cfg = {};
    cfg.gridDim  = dim3(C_CTAS, 1, 1);
    cfg.blockDim = dim3(C_THREADS, 1, 1);
    cfg.dynamicSmemBytes = 0;
    cfg.stream = 0;
    cudaLaunchAttribute attrs[1];
    attrs[0].id = cudaLaunchAttributeClusterDimension;
    attrs[0].val.clusterDim.x = 16;
    attrs[0].val.clusterDim.y = 1;
    attrs[0].val.clusterDim.z = 1;
    cfg.attrs = attrs;
    cfg.numAttrs = 1;

    int nclusters = 0;
    cudaError_t q = cudaOccupancyMaxActiveClusters(&nclusters, tv_cluster, &cfg);
    (void)cudaGetLastError();   // clear any sticky error from the probe

    if (q == cudaSuccess && nclusters >= 8) {
        cudaLaunchKernelEx(&cfg, tv_cluster, f, lam, out);
    } else {
        void* args[] = { (void*)&f, (void*)&lam, (void*)&out };
        cudaLaunchCooperativeKernel((void*)tv_persist,
                                    dim3(NCTAS), dim3(NTHREADS),
                                    args, 0, 0);
    }
}

// round 5
// speedup vs baseline: 1.9173x; 1.0071x over previous
#include <cuda_runtime.h>
#include <cooperative_groups.h>
#include <cstdint>
namespace cg = cooperative_groups;

#define BB 8
#define HH 256
#define WW 256
#define NPIX (BB*HH*WW)
#define N_ITERS 200

__device__ __forceinline__ float clipf(float v, float b) {
    return fminf(fmaxf(v, -b), b);
}
__device__ __forceinline__ int ld_acquire_gpu(const int* p) {
    int v;
    asm volatile("ld.acquire.gpu.global.s32 %0, [%1];" : "=r"(v) : "l"(p) : "memory");
    return v;
}
__device__ __forceinline__ void st_release_gpu(int* p, int v) {
    asm volatile("st.release.gpu.global.s32 [%0], %1;" :: "l"(p), "r"(v) : "memory");
}
__device__ __forceinline__ float ldcg(const float* p) {
    float v;
    asm volatile("ld.global.cg.f32 %0, [%1];" : "=f"(v) : "l"(p) : "memory");
    return v;
}
// Lane-0 spins; broadcast; then per-lane acquire for ordering.
__device__ __forceinline__ void warp_wait_flag(int* p, int target) {
    const int lane = threadIdx.x & 31;
    int v;
    do {
        v = (lane == 0) ? ld_acquire_gpu(p) : 0;
        v = __shfl_sync(0xffffffffu, v, 0);
    } while (v - target < 0);
    (void)ld_acquire_gpu(p);
}

// ===================== FAST PATH: 8-CTA cluster per half-image =====================

#define C_THREADS 512
#define C_CTAS    (BB * 16)          // 128 CTAs = 16 clusters of 8

__device__ float g_vhalo[2][BB][2][WW];   // midline ubar rows: [parity][img][0:row127 | 1:row128][j]
__device__ int   g_cflags[C_CTAS * 32];   // per-CTA monotone progress flags (1 per 128B)

__device__ __forceinline__ uint32_t smem_u32(const void* p) {
    return (uint32_t)__cvta_generic_to_shared(p);
}
__device__ __forceinline__ void dsmem_store(uint32_t laddr, uint32_t rank, float v) {
    uint32_t rem;
    asm volatile("mapa.shared::cluster.u32 %0, %1, %2;" : "=r"(rem) : "r"(laddr), "r"(rank));
    asm volatile("st.shared::cluster.f32 [%0], %1;" :: "r"(rem), "f"(v) : "memory");
}
__device__ __forceinline__ void cluster_sync_() {
    asm volatile("barrier.cluster.arrive.aligned;" ::: "memory");
    asm volatile("barrier.cluster.wait.aligned;"   ::: "memory");
}

__global__ __launch_bounds__(C_THREADS, 1)
void tv_cluster8(const float* __restrict__ f,
                 const float* __restrict__ lam,
                 float* __restrict__ out)
{
    const float SIG  = 0.35355339f;
    const float TAUc = 0.35355339f;
    const float INV  = 1.0f / (1.0f + TAUc);

    // Double-buffered ubar tile with 1-wide ring (rows/cols 0 and 65/66).
    __shared__ float ubs[2][66][67];

    const int bid  = blockIdx.x;
    const int cl   = bid >> 3;        // cluster id (16)
    const int r    = bid & 7;         // rank within cluster
    const int img  = cl >> 1;
    const int half = cl & 1;          // 0: rows 0..127, 1: rows 128..255
    const int tc   = r & 3;           // tile col 0..3
    const int trl  = r >> 2;          // tile row within cluster 0..1
    const int j0   = tc * 64;
    const int i0   = half * 128 + trl * 64;
    const int tid  = threadIdx.x;
    const int tx   = tid & 63;
    const int ty   = tid >> 6;        // 0..7
    const int j    = j0 + tx;
    const int itop = i0 + ty * 8;
    const int base = (img * HH + itop) * WW + j;
    const int srow = 1 + ty * 8;

    // Zero both SMEM buffers (image-boundary ring cells stay 0 forever).
    for (int x = tid; x < 2 * 66 * 67; x += C_THREADS)
        ((float*)ubs)[x] = 0.f;

    // ---- Load state into registers ----
    float u[8], ub[8], pc[8], qc[8], ql[8];
    float fv[8], lamx[8], lamy[8], lams[8];
#pragma unroll
    for (int k = 0; k < 8; k++) {
        const int i   = itop + k;
        const int idx = base + k * WW;
        float fk = f[idx];
        u[k] = ub[k] = fv[k] = fk;
        pc[k] = qc[k] = ql[k] = 0.f;
        lamx[k] = (i < HH - 1) ? lam[idx + WW] : 0.f;
        lamy[k] = (j < WW - 1) ? lam[idx + 1]  : 0.f;
        lams[k] = (j > 0)      ? lam[idx]      : 0.f;
    }
    float pu_top = 0.f;
    const float pu_lam = (itop > 0) ? lam[base] : 0.f;

    const bool up_in = (trl > 0), dn_in = (trl < 1);
    const bool lf = (tc > 0), rt = (tc < 3);
    const bool is_ub_cta = (half == 0 && trl == 1);  // faces midline from above
    const bool is_lt_cta = (half == 1 && trl == 0);  // faces midline from below

    int* myflag   = &g_cflags[bid * 32];
    int* peerflag = is_ub_cta ? &g_cflags[((cl + 1) * 8 + 0 + tc) * 32]
                  : is_lt_cta ? &g_cflags[((cl - 1) * 8 + 4 + tc) * 32]
                  : myflag;

    // Epoch: all flags advance by exactly N_ITERS per replay, start equal.
    const int epoch = *(volatile int*)myflag;

    cluster_sync_();   // ring zeros visible cluster-wide before DSMEM stores

    for (int it = 0; it < N_ITERS; it++) {
        const int s = it & 1;

        // ---- stage interior ubar ----
#pragma unroll
        for (int k = 0; k < 8; k++) ubs[s][srow + k][1 + tx] = ub[k];

        // ---- publish midline rows to global (double-buffered) ----
        if (is_ub_cta && ty == 7) { g_vhalo[s][img][0][j] = ub[7]; __threadfence(); }
        if (is_lt_cta && ty == 0) { g_vhalo[s][img][1][j] = ub[0]; __threadfence(); }

        // ---- DSMEM exports to in-cluster neighbors ----
        if (ty == 0 && up_in) dsmem_store(smem_u32(&ubs[s][65][1 + tx]), r - 4, ub[0]);
        if (ty == 7 && dn_in) dsmem_store(smem_u32(&ubs[s][0][1 + tx]),  r + 4, ub[7]);
        if (tx == 0 && lf) {
#pragma unroll
            for (int k = 0; k < 8; k++)
                dsmem_store(smem_u32(&ubs[s][srow + k][65]), r - 1, ub[k]);
        }
        if (tx == 63 && rt) {
#pragma unroll
            for (int k = 0; k < 8; k++)
                dsmem_store(smem_u32(&ubs[s][srow + k][0]),  r + 1, ub[k]);
        }

        cluster_sync_();   // DSMEM + local SMEM visible; CTA-wide execution barrier

        const int target = epoch + it + 1;
        if (tid == 0) st_release_gpu(myflag, target);

        // ---- midline wait + pull peer row into own ring (same threads read it) ----
        if (is_ub_cta && ty == 7) {
            warp_wait_flag(peerflag, target);
            ubs[s][65][1 + tx] = ldcg(&g_vhalo[s][img][1][j]);
        }
        if (is_lt_cta && ty == 0) {
            warp_wait_flag(peerflag, target);
            ubs[s][0][1 + tx] = ldcg(&g_vhalo[s][img][0][j]);
        }

        // ---- one Chambolle-Pock iteration in registers ----
        float ub_above = ubs[s][srow - 1][1 + tx];
        pu_top = clipf(pu_top + SIG * (ub[0] - ub_above), pu_lam);
        float pu = pu_top;
#pragma unroll
        for (int k = 0; k < 8; k++) {
            float ub_b = (k < 7) ? ub[k + 1] : ubs[s][srow + 8][1 + tx];
            float ub_l = ubs[s][srow + k][tx];
            float ub_r = ubs[s][srow + k][tx + 2];

            pc[k] = clipf(pc[k] + SIG * (ub_b - ub[k]), lamx[k]);
            qc[k] = clipf(qc[k] + SIG * (ub_r - ub[k]), lamy[k]);
            ql[k] = clipf(ql[k] + SIG * (ub[k] - ub_l), lams[k]);

            float div = (pu - pc[k]) + (ql[k] - qc[k]);
            float un  = (u[k] + TAUc * (fv[k] - div)) * INV;
            ub[k] = 2.f * un - u[k];
            u[k]  = un;
            pu    = pc[k];
        }
        // Double buffer + next iteration's cluster.sync covers the SMEM WAR;
        // mutual flag waits cover the g_vhalo WAR.
    }

#pragma unroll
    for (int k = 0; k < 8; k++) out[base + k * WW] = u[k];
}

// ===================== FALLBACK: cooperative grid.sync kernel (547us known-good) =====================

#define TILE_W 64
#define TILE_H 32
#define VPT 8
#define NCTAS 256
#define NTHREADS 256

__device__ float g_halo[2][NPIX];

__global__ __launch_bounds__(NTHREADS, 2)
void tv_persist(const float* __restrict__ f,
                const float* __restrict__ lam,
                float* __restrict__ out)
{
    cg::grid_group grid = cg::this_grid();

    const float SIG  = 0.35355339f;
    const float TAUc = 0.35355339f;
    const float INV  = 1.0f / (1.0f + TAUc);

    __shared__ float ubs[TILE_H + 2][TILE_W + 2];

    const int c  = blockIdx.x;
    const int b  = c >> 5;
    const int t  = c & 31;
    const int j0 = (t & 3) * TILE_W;
    const int i0 = (t >> 2) * TILE_H;
    const int tx = threadIdx.x & 63;
    const int ty = threadIdx.x >> 6;
    const int j    = j0 + tx;
    const int itop = i0 + ty * VPT;

    const int base = (b * HH + itop) * WW + j;
    const int srow = 1 + ty * VPT;

    float u[VPT], ub[VPT], pc[VPT], qc[VPT], ql[VPT];
    float fv[VPT], lamx[VPT], lamy[VPT], lams[VPT];
#pragma unroll
    for (int k = 0; k < VPT; k++) {
        const int i   = itop + k;
        const int idx = base + k * WW;
        float fk = f[idx];
        u[k] = ub[k] = fv[k] = fk;
        pc[k] = qc[k] = ql[k] = 0.f;
        lamx[k] = (i < HH - 1) ? lam[idx + WW] : 0.f;
        lamy[k] = (j < WW - 1) ? lam[idx + 1]  : 0.f;
        lams[k] = (j > 0)      ? lam[idx]      : 0.f;
    }
    float pu_top = 0.f;
    const float pu_lam = (itop > 0) ? lam[base] : 0.f;

    for (int it = 0; it < N_ITERS; it++) {
        float* H = g_halo[it & 1];
#pragma unroll
        for (int k = 0; k < VPT; k++) ubs[srow + k][1 + tx] = ub[k];

        if (ty == 0) H[base] = ub[0];
        if (ty == 3) H[base + (VPT - 1) * WW] = ub[VPT - 1];
        if (tx == 0 || tx == 63) {
#pragma unroll
            for (int k = 0; k < VPT; k++) H[base + k * WW] = ub[k];
        }

        grid.sync();

        const float* Hc = g_halo[it & 1];
        if (ty == 0)
            ubs[0][1 + tx]          = (i0 > 0)             ? Hc[base - WW]       : 0.f;
        if (ty == 3)
            ubs[TILE_H + 1][1 + tx] = (i0 + TILE_H < HH)   ? Hc[base + VPT * WW] : 0.f;
        if (tx == 0) {
#pragma unroll
            for (int k = 0; k < VPT; k++)
                ubs[srow + k][0]          = (j0 > 0)           ? Hc[base + k * WW - 1] : 0.f;
        }
        if (tx == 63) {
#pragma unroll
            for (int k = 0; k < VPT; k++)
                ubs[srow + k][TILE_W + 1] = (j0 + TILE_W < WW) ? Hc[base + k * WW + 1] : 0.f;
        }
        __syncthreads();

        float ub_above = ubs[srow - 1][1 + tx];
        pu_top = clipf(pu_top + SIG * (ub[0] - ub_above), pu_lam);
        float pu = pu_top;
#pragma unroll
        for (int k = 0; k < VPT; k++) {
            float ub_b = (k < VPT - 1) ? ub[k + 1] : ubs[srow + VPT][1 + tx];
            float ub_l = ubs[srow + k][tx];
            float ub_r = ubs[srow + k][2 + tx];

            pc[k] = clipf(pc[k] + SIG * (ub_b - ub[k]), lamx[k]);
            qc[k] = clipf(qc[k] + SIG * (ub_r - ub[k]), lamy[k]);
            ql[k] = clipf(ql[k] + SIG * (ub[k] - ub_l), lams[k]);

            float div = (pu - pc[k]) + (ql[k] - qc[k]);
            float un  = (u[k] + TAUc * (fv[k] - div)) * INV;
            ub[k] = 2.f * un - u[k];
            u[k]  = un;
            pu    = pc[k];
        }
        __syncthreads();
    }

#pragma unroll
    for (int k = 0; k < VPT; k++) out[base + k * WW] = u[k];
}

// ===================== host =====================

extern "C" void kernel_launch(void* const* d_in, const int* in_sizes, int n_in,
                              void* d_out, int out_size) {
    const float* f   = (const float*)d_in[0];
    const float* lam = (const float*)d_in[1];
    float* out = (float*)d_out;

    cudaLaunchConfig_t cfg = {};
    cfg.gridDim  = dim3(C_CTAS, 1, 1);
    cfg.blockDim = dim3(C_THREADS, 1, 1);
    cfg.dynamicSmemBytes = 0;
    cfg.stream = 0;
    cudaLaunchAttribute attrs[1];
    attrs[0].id = cudaLaunchAttributeClusterDimension;
    attrs[0].val.clusterDim.x = 8;   // portable cluster size
    attrs[0].val.clusterDim.y = 1;
    attrs[0].val.clusterDim.z = 1;
    cfg.attrs = attrs;
    cfg.numAttrs = 1;

    int nclusters = 0;
    cudaError_t q = cudaOccupancyMaxActiveClusters(&nclusters, tv_cluster8, &cfg);
    (void)cudaGetLastError();

    if (q == cudaSuccess && nclusters >= 16) {
        cudaLaunchKernelEx(&cfg, tv_cluster8, f, lam, out);
    } else {
        void* args[] = { (void*)&f, (void*)&lam, (void*)&out };
        cudaLaunchCooperativeKernel((void*)tv_persist,
                                    dim3(NCTAS), dim3(NTHREADS),
                                    args, 0, 0);
    }
}